// round 1
// baseline (speedup 1.0000x reference)
#include <cuda_runtime.h>
#include <cstdint>

#define T_STEPS 1000
#define BATCH   8192
#define IN      9
#define HID     96
#define OUTD    3
#define HS      12   // hidden units per thread
#define GRP     8    // threads per batch element
#define HP      6    // f32x2 pairs per thread (HS/2)

typedef unsigned long long u64;

__device__ __forceinline__ u64 pack2(float lo, float hi) {
    u64 r;
    asm("mov.b64 %0, {%1, %2};" : "=l"(r)
        : "r"(__float_as_uint(lo)), "r"(__float_as_uint(hi)));
    return r;
}
__device__ __forceinline__ void unpack2(u64 v, float& lo, float& hi) {
    unsigned a, b;
    asm("mov.b64 {%0, %1}, %2;" : "=r"(a), "=r"(b) : "l"(v));
    lo = __uint_as_float(a);
    hi = __uint_as_float(b);
}
__device__ __forceinline__ u64 ffma2(u64 a, u64 b, u64 c) {
    u64 d;
    asm("fma.rn.f32x2 %0, %1, %2, %3;" : "=l"(d) : "l"(a), "l"(b), "l"(c));
    return d;
}

__global__ __launch_bounds__(128)
void snn_kernel(const float* __restrict__ X,
                const float* __restrict__ W1,
                const float* __restrict__ B1,
                const float* __restrict__ W2,
                const float* __restrict__ B2,
                float* __restrict__ out)
{
    const int tid  = blockIdx.x * blockDim.x + threadIdx.x;
    const int b    = tid >> 3;      // batch element
    const int pos  = tid & 7;       // position within 8-thread group
    const int hbase = pos * HS;

    // ---- Load weight slices into registers (once) ----
    u64 w1p[IN][HP];
#pragma unroll
    for (int j = 0; j < HP; j++) {
        const int h0 = hbase + 2 * j;
#pragma unroll
        for (int i = 0; i < IN; i++)
            w1p[i][j] = pack2(W1[h0 * IN + i], W1[(h0 + 1) * IN + i]);
    }
    u64 b1p[HP];
#pragma unroll
    for (int j = 0; j < HP; j++)
        b1p[j] = pack2(B1[hbase + 2 * j], B1[hbase + 2 * j + 1]);

    u64 w2p[OUTD][HP];
#pragma unroll
    for (int o = 0; o < OUTD; o++)
#pragma unroll
        for (int j = 0; j < HP; j++)
            w2p[o][j] = pack2(W2[o * HID + hbase + 2 * j],
                              W2[o * HID + hbase + 2 * j + 1]);

    const float b2r0 = B2[0], b2r1 = B2[1], b2r2 = B2[2];

    const u64 BETA2 = pack2(0.92f, 0.92f);
    const u64 NEG12 = pack2(-1.0f, -1.0f);

    // ---- State ----
    u64 mp[HP], sp[HP];
#pragma unroll
    for (int j = 0; j < HP; j++) { mp[j] = 0ull; sp[j] = 0ull; }
    float m20 = 0.f, m21 = 0.f, m22 = 0.f;
    float s20 = 0.f, s21 = 0.f, s22 = 0.f;

    const float* xptr = X + (size_t)b * IN;
    const size_t xstride = (size_t)BATCH * IN;
    const size_t outb = (size_t)b * OUTD;
    const size_t memoff = (size_t)T_STEPS * BATCH * OUTD;

    // prefetch t = 0
    float nx[IN];
#pragma unroll
    for (int i = 0; i < IN; i++) nx[i] = __ldg(xptr + i);

#pragma unroll 1
    for (int t = 0; t < T_STEPS; t++) {
        // consume prefetched x into duplicated f32x2 regs
        u64 xd[IN];
#pragma unroll
        for (int i = 0; i < IN; i++) xd[i] = pack2(nx[i], nx[i]);

        // prefetch next timestep
        if (t + 1 < T_STEPS) {
            const float* nxt = xptr + (size_t)(t + 1) * xstride;
#pragma unroll
            for (int i = 0; i < IN; i++) nx[i] = __ldg(nxt + i);
        }

        // mem1 = beta*mem1 + b1 - spk_prev*1 + x @ W1_slice  (packed pairs)
#pragma unroll
        for (int j = 0; j < HP; j++) {
            u64 m = ffma2(BETA2, mp[j], b1p[j]);
            m = ffma2(sp[j], NEG12, m);
#pragma unroll
            for (int i = 0; i < IN; i++)
                m = ffma2(xd[i], w1p[i][j], m);
            mp[j] = m;
        }

        // spikes (spk = mem1 > 1), reused as next step's reset; layer-2 partials
        u64 c0 = 0ull, c1 = 0ull, c2 = 0ull;
#pragma unroll
        for (int j = 0; j < HP; j++) {
            float a, bq;
            unpack2(mp[j], a, bq);
            const float sa = (a  > 1.0f) ? 1.0f : 0.0f;
            const float sb = (bq > 1.0f) ? 1.0f : 0.0f;
            const u64 s = pack2(sa, sb);
            sp[j] = s;
            c0 = ffma2(s, w2p[0][j], c0);
            c1 = ffma2(s, w2p[1][j], c1);
            c2 = ffma2(s, w2p[2][j], c2);
        }
        float a0, b0, a1, b1v, a2, b2v;
        unpack2(c0, a0, b0);
        unpack2(c1, a1, b1v);
        unpack2(c2, a2, b2v);
        float cur0 = a0 + b0, cur1 = a1 + b1v, cur2 = a2 + b2v;

        // reduce layer-2 partials across the 8-lane group
        cur0 += __shfl_xor_sync(0xffffffffu, cur0, 1);
        cur1 += __shfl_xor_sync(0xffffffffu, cur1, 1);
        cur2 += __shfl_xor_sync(0xffffffffu, cur2, 1);
        cur0 += __shfl_xor_sync(0xffffffffu, cur0, 2);
        cur1 += __shfl_xor_sync(0xffffffffu, cur1, 2);
        cur2 += __shfl_xor_sync(0xffffffffu, cur2, 2);
        cur0 += __shfl_xor_sync(0xffffffffu, cur0, 4);
        cur1 += __shfl_xor_sync(0xffffffffu, cur1, 4);
        cur2 += __shfl_xor_sync(0xffffffffu, cur2, 4);

        // mem2 update (replicated across the 8 lanes; rst2 == prev spk2)
        m20 = fmaf(0.92f, m20, cur0 + b2r0) - s20;
        m21 = fmaf(0.92f, m21, cur1 + b2r1) - s21;
        m22 = fmaf(0.92f, m22, cur2 + b2r2) - s22;
        s20 = (m20 > 1.0f) ? 1.0f : 0.0f;
        s21 = (m21 > 1.0f) ? 1.0f : 0.0f;
        s22 = (m22 > 1.0f) ? 1.0f : 0.0f;

        // distributed store: lanes 0-2 write spk2, lanes 3-5 write mem2
        float val = s20;
        val = (pos == 1) ? s21 : val;
        val = (pos == 2) ? s22 : val;
        val = (pos == 3) ? m20 : val;
        val = (pos == 4) ? m21 : val;
        val = (pos == 5) ? m22 : val;
        const size_t base = (size_t)t * (BATCH * OUTD) + outb;
        const size_t addr = base + (size_t)((pos < 3) ? pos : pos - 3)
                          + ((pos < 3) ? 0 : memoff);
        if (pos < 6) out[addr] = val;
    }
}

extern "C" void kernel_launch(void* const* d_in, const int* in_sizes, int n_in,
                              void* d_out, int out_size)
{
    const float* X  = (const float*)d_in[0];
    const float* W1 = (const float*)d_in[1];
    const float* B1 = (const float*)d_in[2];
    const float* W2 = (const float*)d_in[3];
    const float* B2 = (const float*)d_in[4];
    float* out = (float*)d_out;

    const int threads = 128;
    const int blocks  = (BATCH * GRP) / threads;  // 512
    snn_kernel<<<blocks, threads>>>(X, W1, B1, W2, B2, out);
}